// round 1
// baseline (speedup 1.0000x reference)
#include <cuda_runtime.h>

#define S_LEN   2048
#define BATCH   2
#define DMODEL  1024
#define NHEADS  16
#define DK      64
#define NTOK    (BATCH * S_LEN)      // 4096
#define QKV_N   (3 * DMODEL)         // 3072

// Scratch (allocation-free rule: __device__ globals)
__device__ float g_qkv[(size_t)NTOK * QKV_N];   // [token][3*D]  (q | k | v)
__device__ float g_att[(size_t)NTOK * DMODEL];  // attention output, [token][h*64+d]

// ---------------------------------------------------------------------------
// SGEMM: C[M,N] = A[M,K] @ B[K,N] (+ bias[N] if bias != nullptr)
// 128x128 block tile, BK=8, 256 threads, 8x8 per-thread micro tile.
// Requires M%128==0, N%128==0, K%8==0 (true for all three calls here).
// ---------------------------------------------------------------------------
__global__ __launch_bounds__(256) void sgemm_bias_kernel(
    const float* __restrict__ A, const float* __restrict__ B,
    const float* __restrict__ bias, float* __restrict__ C,
    int M, int N, int K)
{
    __shared__ float As[8][132];   // transposed A tile, padded
    __shared__ float Bs[8][128];

    const int tid = threadIdx.x;
    const int tx  = tid & 15;      // 0..15 -> 8 output cols each
    const int ty  = tid >> 4;      // 0..15 -> 8 output rows each
    const int m0  = blockIdx.y * 128;
    const int n0  = blockIdx.x * 128;

    const int aRow = tid >> 1;            // 0..127
    const int aCol = (tid & 1) * 4;       // 0 or 4
    const int bRow = tid >> 5;            // 0..7
    const int bCol = (tid & 31) * 4;      // 0..124

    const float* Aptr = A + (size_t)(m0 + aRow) * K + aCol;
    const float* Bptr = B + (size_t)bRow * N + n0 + bCol;

    float acc[8][8];
#pragma unroll
    for (int i = 0; i < 8; i++)
#pragma unroll
        for (int j = 0; j < 8; j++) acc[i][j] = 0.f;

    for (int k0 = 0; k0 < K; k0 += 8) {
        float4 av = *(const float4*)(Aptr + k0);
        As[aCol + 0][aRow] = av.x;
        As[aCol + 1][aRow] = av.y;
        As[aCol + 2][aRow] = av.z;
        As[aCol + 3][aRow] = av.w;
        float4 bv = *(const float4*)(Bptr + (size_t)k0 * N);
        *(float4*)&Bs[bRow][bCol] = bv;
        __syncthreads();

#pragma unroll
        for (int kk = 0; kk < 8; kk++) {
            float ar[8], br[8];
#pragma unroll
            for (int i = 0; i < 8; i++) ar[i] = As[kk][ty * 8 + i];
#pragma unroll
            for (int j = 0; j < 8; j++) br[j] = Bs[kk][tx * 8 + j];
#pragma unroll
            for (int i = 0; i < 8; i++)
#pragma unroll
                for (int j = 0; j < 8; j++) acc[i][j] += ar[i] * br[j];
        }
        __syncthreads();
    }

    float bb[8];
#pragma unroll
    for (int j = 0; j < 8; j++) bb[j] = bias ? bias[n0 + tx * 8 + j] : 0.f;

#pragma unroll
    for (int i = 0; i < 8; i++) {
        float* crow = C + (size_t)(m0 + ty * 8 + i) * N + n0 + tx * 8;
        float4 v0 = make_float4(acc[i][0] + bb[0], acc[i][1] + bb[1],
                                acc[i][2] + bb[2], acc[i][3] + bb[3]);
        float4 v1 = make_float4(acc[i][4] + bb[4], acc[i][5] + bb[5],
                                acc[i][6] + bb[6], acc[i][7] + bb[7]);
        *(float4*)(crow)     = v0;
        *(float4*)(crow + 4) = v1;
    }
}

// ---------------------------------------------------------------------------
// Flash attention (fp32, online softmax).
// Grid: (S/64, B*H). Block: 256 threads = 16x16; each thread owns a 4x4
// micro tile of the 64x64 score tile AND a 4x4 tile of the 64x64 output.
// Dynamic smem: Qs,Ks,Vs,Ps each 64x65 floats = 66560 bytes.
// ---------------------------------------------------------------------------
__global__ __launch_bounds__(256) void attn_kernel(
    const float* __restrict__ qkv, float* __restrict__ out)
{
    extern __shared__ float sm[];
    float* Qs = sm;                // [64][65]  (pre-scaled by 1/sqrt(dk))
    float* Ks = Qs + 64 * 65;      // [64][65]
    float* Vs = Ks + 64 * 65;      // [64][65]
    float* Ps = Vs + 64 * 65;      // [64][65]

    const int tid = threadIdx.x;
    const int tx  = tid & 15;      // 0..15 -> 4 cols each
    const int ty  = tid >> 4;      // 0..15 -> 4 rows each
    const int bh  = blockIdx.y;
    const int b   = bh >> 4;
    const int h   = bh & 15;
    const int q0  = blockIdx.x * 64;

    const float* Qg = qkv + (size_t)b * S_LEN * QKV_N + h * DK;
    const float* Kg = Qg + DMODEL;
    const float* Vg = Qg + 2 * DMODEL;

    // Load Q tile (scaled)
    for (int i = tid; i < 64 * 64; i += 256) {
        int r = i >> 6, d = i & 63;
        Qs[r * 65 + d] = Qg[(size_t)(q0 + r) * QKV_N + d] * 0.125f;
    }

    float m_i[4], l_i[4], o[4][4];
#pragma unroll
    for (int i = 0; i < 4; i++) {
        m_i[i] = -1e30f;
        l_i[i] = 0.f;
#pragma unroll
        for (int j = 0; j < 4; j++) o[i][j] = 0.f;
    }

    for (int kt = 0; kt < S_LEN / 64; kt++) {
        const int kv0 = kt * 64;
        __syncthreads();  // previous iteration done reading Ks/Vs/Ps (covers iter 0 trivially)
        for (int i = tid; i < 64 * 64; i += 256) {
            int r = i >> 6, d = i & 63;
            Ks[r * 65 + d] = Kg[(size_t)(kv0 + r) * QKV_N + d];
            Vs[r * 65 + d] = Vg[(size_t)(kv0 + r) * QKV_N + d];
        }
        __syncthreads();

        // S = (Q * scale) @ K^T, 4x4 per thread
        float sacc[4][4];
#pragma unroll
        for (int i = 0; i < 4; i++)
#pragma unroll
            for (int j = 0; j < 4; j++) sacc[i][j] = 0.f;

#pragma unroll 8
        for (int d = 0; d < 64; d++) {
            float qf[4], kf[4];
#pragma unroll
            for (int i = 0; i < 4; i++) qf[i] = Qs[(ty * 4 + i) * 65 + d];
#pragma unroll
            for (int j = 0; j < 4; j++) kf[j] = Ks[(tx * 4 + j) * 65 + d];
#pragma unroll
            for (int i = 0; i < 4; i++)
#pragma unroll
                for (int j = 0; j < 4; j++) sacc[i][j] += qf[i] * kf[j];
        }

        // Online softmax update (row groups of 16 lanes share a row)
#pragma unroll
        for (int i = 0; i < 4; i++) {
            float rm = sacc[i][0];
#pragma unroll
            for (int j = 1; j < 4; j++) rm = fmaxf(rm, sacc[i][j]);
#pragma unroll
            for (int off = 8; off > 0; off >>= 1)
                rm = fmaxf(rm, __shfl_xor_sync(0xffffffffu, rm, off, 16));

            float mnew = fmaxf(m_i[i], rm);
            float corr = __expf(m_i[i] - mnew);
            m_i[i] = mnew;

            float rs = 0.f;
#pragma unroll
            for (int j = 0; j < 4; j++) {
                float p = __expf(sacc[i][j] - mnew);
                Ps[(ty * 4 + i) * 65 + tx * 4 + j] = p;
                rs += p;
            }
#pragma unroll
            for (int off = 8; off > 0; off >>= 1)
                rs += __shfl_xor_sync(0xffffffffu, rs, off, 16);

            l_i[i] = l_i[i] * corr + rs;
#pragma unroll
            for (int j = 0; j < 4; j++) o[i][j] *= corr;
        }
        __syncthreads();  // Ps fully written

        // O += P @ V
#pragma unroll 8
        for (int c = 0; c < 64; c++) {
            float pf[4], vf[4];
#pragma unroll
            for (int i = 0; i < 4; i++) pf[i] = Ps[(ty * 4 + i) * 65 + c];
#pragma unroll
            for (int j = 0; j < 4; j++) vf[j] = Vs[c * 65 + tx * 4 + j];
#pragma unroll
            for (int i = 0; i < 4; i++)
#pragma unroll
                for (int j = 0; j < 4; j++) o[i][j] += pf[i] * vf[j];
        }
    }

    // Normalize and write: out[token][h*64 + d]
#pragma unroll
    for (int i = 0; i < 4; i++) {
        float inv = 1.f / l_i[i];
        int token = b * S_LEN + q0 + ty * 4 + i;
        float* op = out + (size_t)token * DMODEL + h * DK + tx * 4;
#pragma unroll
        for (int j = 0; j < 4; j++) op[j] = o[i][j] * inv;
    }
}

// ---------------------------------------------------------------------------
extern "C" void kernel_launch(void* const* d_in, const int* in_sizes, int n_in,
                              void* d_out, int out_size)
{
    const float* input = (const float*)d_in[0];   // [2,2048,1024]
    const float* W_qkv = (const float*)d_in[1];   // [1024,3072]
    const float* b_qkv = (const float*)d_in[2];   // [3072]
    const float* W_out = (const float*)d_in[3];   // [1024,1024]
    float* out = (float*)d_out;                   // [2,2048,1024]

    float *qkv_buf, *att_buf;
    cudaGetSymbolAddress((void**)&qkv_buf, g_qkv);
    cudaGetSymbolAddress((void**)&att_buf, g_att);

    // 1) QKV projection + bias
    sgemm_bias_kernel<<<dim3(QKV_N / 128, NTOK / 128), 256>>>(
        input, W_qkv, b_qkv, qkv_buf, NTOK, QKV_N, DMODEL);

    // 2) Flash attention
    const int smem = 4 * 64 * 65 * (int)sizeof(float);   // 66560 B
    cudaFuncSetAttribute(attn_kernel,
                         cudaFuncAttributeMaxDynamicSharedMemorySize, smem);
    attn_kernel<<<dim3(S_LEN / 64, BATCH * NHEADS), 256, smem>>>(qkv_buf, att_buf);

    // 3) Output projection (no bias)
    sgemm_bias_kernel<<<dim3(DMODEL / 128, NTOK / 128), 256>>>(
        att_buf, W_out, nullptr, out, NTOK, DMODEL, DMODEL);
}

// round 2
// speedup vs baseline: 2.9831x; 2.9831x over previous
#include <cuda_runtime.h>
#include <stdint.h>

#define S_LEN   2048
#define BATCH   2
#define DMODEL  1024
#define NHEADS  16
#define DK      64
#define NTOK    (BATCH * S_LEN)      // 4096
#define QKV_N   (3 * DMODEL)         // 3072

// Scratch (allocation-free rule: __device__ globals)
__device__ float g_qkv[(size_t)NTOK * QKV_N];   // [token][3*D]  (q | k | v)
__device__ float g_att[(size_t)NTOK * DMODEL];  // attention output, [token][h*64+d]

// ---------------------------------------------------------------------------
// tf32 helpers
// ---------------------------------------------------------------------------
__device__ __forceinline__ uint32_t f2t(float x) {
    uint32_t r;
    asm("cvt.rna.tf32.f32 %0, %1;" : "=r"(r) : "f"(x));
    return r;
}

// D = A(16x8) * B(8x8) + D, row.col, fp32 accumulate
__device__ __forceinline__ void mma8(float* c, const uint32_t* a, const uint32_t* b) {
    asm volatile(
        "mma.sync.aligned.m16n8k8.row.col.f32.tf32.tf32.f32 "
        "{%0,%1,%2,%3}, {%4,%5,%6,%7}, {%8,%9}, {%0,%1,%2,%3};"
        : "+f"(c[0]), "+f"(c[1]), "+f"(c[2]), "+f"(c[3])
        : "r"(a[0]), "r"(a[1]), "r"(a[2]), "r"(a[3]), "r"(b[0]), "r"(b[1]));
}

// ---------------------------------------------------------------------------
// TF32 tensor-core GEMM: C[M,N] = A[M,K] @ B[K,N] (+bias)
// 128x128x32 block tile, 256 threads = 8 warps (4x2), warp tile 32x64.
// Fragment loads are bank-conflict-free: As stride 36 (=4 mod 32),
// Bs stride 136 (=8 mod 32).
// ---------------------------------------------------------------------------
__global__ __launch_bounds__(256) void gemm_tf32(
    const float* __restrict__ A, const float* __restrict__ B,
    const float* __restrict__ bias, float* __restrict__ C,
    int M, int N, int K)
{
    __shared__ uint32_t As[128][36];
    __shared__ uint32_t Bs[32][136];

    const int tid  = threadIdx.x;
    const int lane = tid & 31;
    const int wid  = tid >> 5;
    const int wm   = (wid & 3) * 32;     // warp row origin in tile
    const int wn   = (wid >> 2) * 64;    // warp col origin in tile
    const int g    = lane >> 2;          // 0..7
    const int q    = lane & 3;           // 0..3
    const int m0   = blockIdx.y * 128;
    const int n0   = blockIdx.x * 128;

    float acc[2][8][4];
#pragma unroll
    for (int mt = 0; mt < 2; mt++)
#pragma unroll
        for (int nt = 0; nt < 8; nt++)
#pragma unroll
            for (int i = 0; i < 4; i++) acc[mt][nt][i] = 0.f;

    for (int k0 = 0; k0 < K; k0 += 32) {
        // A tile 128x32 : 1024 float4, 4 per thread
#pragma unroll
        for (int i = 0; i < 4; i++) {
            int f = tid + i * 256;
            int r = f >> 3, c = (f & 7) * 4;
            float4 v = *(const float4*)(A + (size_t)(m0 + r) * K + k0 + c);
            As[r][c + 0] = f2t(v.x); As[r][c + 1] = f2t(v.y);
            As[r][c + 2] = f2t(v.z); As[r][c + 3] = f2t(v.w);
        }
        // B tile 32x128
#pragma unroll
        for (int i = 0; i < 4; i++) {
            int f = tid + i * 256;
            int r = f >> 5, c = (f & 31) * 4;
            float4 v = *(const float4*)(B + (size_t)(k0 + r) * N + n0 + c);
            Bs[r][c + 0] = f2t(v.x); Bs[r][c + 1] = f2t(v.y);
            Bs[r][c + 2] = f2t(v.z); Bs[r][c + 3] = f2t(v.w);
        }
        __syncthreads();

#pragma unroll
        for (int kk = 0; kk < 4; kk++) {
            uint32_t a[2][4], b[8][2];
#pragma unroll
            for (int mt = 0; mt < 2; mt++) {
                int r = wm + mt * 16 + g;
                a[mt][0] = As[r][kk * 8 + q];
                a[mt][1] = As[r + 8][kk * 8 + q];
                a[mt][2] = As[r][kk * 8 + q + 4];
                a[mt][3] = As[r + 8][kk * 8 + q + 4];
            }
#pragma unroll
            for (int nt = 0; nt < 8; nt++) {
                int c = wn + nt * 8 + g;
                b[nt][0] = Bs[kk * 8 + q][c];
                b[nt][1] = Bs[kk * 8 + q + 4][c];
            }
#pragma unroll
            for (int mt = 0; mt < 2; mt++)
#pragma unroll
                for (int nt = 0; nt < 8; nt++)
                    mma8(acc[mt][nt], a[mt], b[nt]);
        }
        __syncthreads();
    }

    // Epilogue: c0 (r, 2q), c1 (r, 2q+1), c2 (r+8, 2q), c3 (r+8, 2q+1)
#pragma unroll
    for (int mt = 0; mt < 2; mt++) {
#pragma unroll
        for (int nt = 0; nt < 8; nt++) {
            int row = m0 + wm + mt * 16 + g;
            int col = n0 + wn + nt * 8 + 2 * q;
            float b0 = bias ? bias[col] : 0.f;
            float b1 = bias ? bias[col + 1] : 0.f;
            float2 v0 = make_float2(acc[mt][nt][0] + b0, acc[mt][nt][1] + b1);
            float2 v1 = make_float2(acc[mt][nt][2] + b0, acc[mt][nt][3] + b1);
            *(float2*)(C + (size_t)row * N + col) = v0;
            *(float2*)(C + (size_t)(row + 8) * N + col) = v1;
        }
    }
}

// ---------------------------------------------------------------------------
// Flash attention with tf32 mma. Grid (S/64, B*H), 128 threads = 4 warps.
// Warp w owns query rows [16w, 16w+16). Per kv-tile of 64:
//   S = Q K^T (mma), online softmax in registers, P -> smem, O += P V (mma).
// Smem strides: Qs/Ks/Ps 68 (=4 mod 32), Vs 72 (=8 mod 32) -> conflict-free frags.
// ---------------------------------------------------------------------------
#define QS_OFF 0
#define KS_OFF (64 * 68)
#define VS_OFF (KS_OFF + 64 * 68)
#define PS_OFF (VS_OFF + 64 * 72)
#define SMEM_U32 (PS_OFF + 64 * 68)   // 17664 u32 = 70656 B

__global__ __launch_bounds__(128) void attn_tf32(
    const float* __restrict__ qkv, float* __restrict__ out)
{
    extern __shared__ uint32_t sm[];
    uint32_t* Qs = sm + QS_OFF;   // [64][68]
    uint32_t* Ks = sm + KS_OFF;   // [64][68]
    uint32_t* Vs = sm + VS_OFF;   // [64][72]
    uint32_t* Ps = sm + PS_OFF;   // [64][68]

    const int tid  = threadIdx.x;
    const int lane = tid & 31;
    const int wid  = tid >> 5;
    const int g    = lane >> 2;
    const int q    = lane & 3;
    const int wr   = wid * 16;           // warp's query-row origin in tile
    const int bh   = blockIdx.y;
    const int b    = bh >> 4;
    const int h    = bh & 15;
    const int q0   = blockIdx.x * 64;

    const float* Qg = qkv + (size_t)b * S_LEN * QKV_N + h * DK;
    const float* Kg = Qg + DMODEL;
    const float* Vg = Qg + 2 * DMODEL;

    // Load Q tile, pre-scaled by 1/sqrt(dk)=0.125
#pragma unroll
    for (int i = 0; i < 8; i++) {
        int f = tid + i * 128;
        int r = f >> 4, c = (f & 15) * 4;
        float4 v = *(const float4*)(Qg + (size_t)(q0 + r) * QKV_N + c);
        Qs[r * 68 + c + 0] = f2t(v.x * 0.125f);
        Qs[r * 68 + c + 1] = f2t(v.y * 0.125f);
        Qs[r * 68 + c + 2] = f2t(v.z * 0.125f);
        Qs[r * 68 + c + 3] = f2t(v.w * 0.125f);
    }

    float m_i[2] = {-1e30f, -1e30f};
    float l_i[2] = {0.f, 0.f};
    float o[8][4];
#pragma unroll
    for (int nt = 0; nt < 8; nt++)
#pragma unroll
        for (int i = 0; i < 4; i++) o[nt][i] = 0.f;

    for (int kt = 0; kt < S_LEN / 64; kt++) {
        const int kv0 = kt * 64;
        __syncthreads();   // previous iter done reading Ks/Vs (also orders Qs on iter 0)
#pragma unroll
        for (int i = 0; i < 8; i++) {
            int f = tid + i * 128;
            int r = f >> 4, c = (f & 15) * 4;
            float4 kv = *(const float4*)(Kg + (size_t)(kv0 + r) * QKV_N + c);
            float4 vv = *(const float4*)(Vg + (size_t)(kv0 + r) * QKV_N + c);
            Ks[r * 68 + c + 0] = f2t(kv.x); Ks[r * 68 + c + 1] = f2t(kv.y);
            Ks[r * 68 + c + 2] = f2t(kv.z); Ks[r * 68 + c + 3] = f2t(kv.w);
            Vs[r * 72 + c + 0] = f2t(vv.x); Vs[r * 72 + c + 1] = f2t(vv.y);
            Vs[r * 72 + c + 2] = f2t(vv.z); Vs[r * 72 + c + 3] = f2t(vv.w);
        }
        __syncthreads();

        // ---- S = Q K^T : warp computes 16x64 ----
        float sacc[8][4];
#pragma unroll
        for (int nt = 0; nt < 8; nt++)
#pragma unroll
            for (int i = 0; i < 4; i++) sacc[nt][i] = 0.f;

#pragma unroll
        for (int kk = 0; kk < 8; kk++) {
            uint32_t a[4], bfr[2];
            int r = wr + g;
            a[0] = Qs[r * 68 + kk * 8 + q];
            a[1] = Qs[(r + 8) * 68 + kk * 8 + q];
            a[2] = Qs[r * 68 + kk * 8 + q + 4];
            a[3] = Qs[(r + 8) * 68 + kk * 8 + q + 4];
#pragma unroll
            for (int nt = 0; nt < 8; nt++) {
                bfr[0] = Ks[(nt * 8 + g) * 68 + kk * 8 + q];
                bfr[1] = Ks[(nt * 8 + g) * 68 + kk * 8 + q + 4];
                mma8(sacc[nt], a, bfr);
            }
        }

        // ---- online softmax (rows r0=wr+g, r1=r0+8) ----
#pragma unroll
        for (int rh = 0; rh < 2; rh++) {
            int row = wr + g + 8 * rh;
            float rm = -1e30f;
#pragma unroll
            for (int nt = 0; nt < 8; nt++)
                rm = fmaxf(rm, fmaxf(sacc[nt][2 * rh], sacc[nt][2 * rh + 1]));
            rm = fmaxf(rm, __shfl_xor_sync(0xffffffffu, rm, 1));
            rm = fmaxf(rm, __shfl_xor_sync(0xffffffffu, rm, 2));

            float mnew = fmaxf(m_i[rh], rm);
            float corr = __expf(m_i[rh] - mnew);
            m_i[rh] = mnew;

            float rs = 0.f;
#pragma unroll
            for (int nt = 0; nt < 8; nt++) {
                float p0 = __expf(sacc[nt][2 * rh] - mnew);
                float p1 = __expf(sacc[nt][2 * rh + 1] - mnew);
                Ps[row * 68 + nt * 8 + 2 * q]     = f2t(p0);
                Ps[row * 68 + nt * 8 + 2 * q + 1] = f2t(p1);
                rs += p0 + p1;
            }
            rs += __shfl_xor_sync(0xffffffffu, rs, 1);
            rs += __shfl_xor_sync(0xffffffffu, rs, 2);
            l_i[rh] = l_i[rh] * corr + rs;
#pragma unroll
            for (int nt = 0; nt < 8; nt++) {
                o[nt][2 * rh]     *= corr;
                o[nt][2 * rh + 1] *= corr;
            }
        }
        __syncwarp();   // Ps rows are warp-private; warp-level visibility suffices

        // ---- O += P V ----
#pragma unroll
        for (int kk = 0; kk < 8; kk++) {
            uint32_t a[4], bfr[2];
            int r = wr + g;
            a[0] = Ps[r * 68 + kk * 8 + q];
            a[1] = Ps[(r + 8) * 68 + kk * 8 + q];
            a[2] = Ps[r * 68 + kk * 8 + q + 4];
            a[3] = Ps[(r + 8) * 68 + kk * 8 + q + 4];
#pragma unroll
            for (int nt = 0; nt < 8; nt++) {
                bfr[0] = Vs[(kk * 8 + q) * 72 + nt * 8 + g];
                bfr[1] = Vs[(kk * 8 + q + 4) * 72 + nt * 8 + g];
                mma8(o[nt], a, bfr);
            }
        }
    }

    // ---- normalize + write out[token][h*64 + col] ----
#pragma unroll
    for (int rh = 0; rh < 2; rh++) {
        float inv = 1.f / l_i[rh];
        int token = b * S_LEN + q0 + wr + g + 8 * rh;
        float* op = out + (size_t)token * DMODEL + h * DK;
#pragma unroll
        for (int nt = 0; nt < 8; nt++) {
            float2 v = make_float2(o[nt][2 * rh] * inv, o[nt][2 * rh + 1] * inv);
            *(float2*)(op + nt * 8 + 2 * q) = v;
        }
    }
}

// ---------------------------------------------------------------------------
extern "C" void kernel_launch(void* const* d_in, const int* in_sizes, int n_in,
                              void* d_out, int out_size)
{
    const float* input = (const float*)d_in[0];   // [2,2048,1024]
    const float* W_qkv = (const float*)d_in[1];   // [1024,3072]
    const float* b_qkv = (const float*)d_in[2];   // [3072]
    const float* W_out = (const float*)d_in[3];   // [1024,1024]
    float* out = (float*)d_out;                   // [2,2048,1024]

    float *qkv_buf, *att_buf;
    cudaGetSymbolAddress((void**)&qkv_buf, g_qkv);
    cudaGetSymbolAddress((void**)&att_buf, g_att);

    // 1) QKV projection + bias
    gemm_tf32<<<dim3(QKV_N / 128, NTOK / 128), 256>>>(
        input, W_qkv, b_qkv, qkv_buf, NTOK, QKV_N, DMODEL);

    // 2) Flash attention (tf32 mma)
    const int smem = SMEM_U32 * (int)sizeof(uint32_t);   // 70656 B
    cudaFuncSetAttribute(attn_tf32,
                         cudaFuncAttributeMaxDynamicSharedMemorySize, smem);
    attn_tf32<<<dim3(S_LEN / 64, BATCH * NHEADS), 128, smem>>>(qkv_buf, att_buf);

    // 3) Output projection (no bias)
    gemm_tf32<<<dim3(DMODEL / 128, NTOK / 128), 256>>>(
        att_buf, W_out, nullptr, out, NTOK, DMODEL, DMODEL);
}

// round 3
// speedup vs baseline: 3.5362x; 1.1854x over previous
#include <cuda_runtime.h>
#include <stdint.h>

#define S_LEN   2048
#define BATCH   2
#define DMODEL  1024
#define NHEADS  16
#define DK      64
#define NTOK    (BATCH * S_LEN)      // 4096
#define QKV_N   (3 * DMODEL)         // 3072

// Scratch (allocation-free rule: __device__ globals)
__device__ float g_qkv[(size_t)NTOK * QKV_N];     // [token][3*D], tf32-rounded
__device__ float g_att[(size_t)NTOK * DMODEL];    // attn out, tf32-rounded
__device__ float g_in_r[(size_t)NTOK * DMODEL];   // rounded input
__device__ float g_wqkv_r[(size_t)DMODEL * QKV_N];
__device__ float g_wout_r[(size_t)DMODEL * DMODEL];

// ---------------------------------------------------------------------------
__device__ __forceinline__ uint32_t f2t(float x) {
    uint32_t r;
    asm("cvt.rna.tf32.f32 %0, %1;" : "=r"(r) : "f"(x));
    return r;
}
__device__ __forceinline__ float roundtf(float x) { return __uint_as_float(f2t(x)); }

__device__ __forceinline__ void mma8(float* c, const uint32_t* a, const uint32_t* b) {
    asm volatile(
        "mma.sync.aligned.m16n8k8.row.col.f32.tf32.tf32.f32 "
        "{%0,%1,%2,%3}, {%4,%5,%6,%7}, {%8,%9}, {%0,%1,%2,%3};"
        : "+f"(c[0]), "+f"(c[1]), "+f"(c[2]), "+f"(c[3])
        : "r"(a[0]), "r"(a[1]), "r"(a[2]), "r"(a[3]), "r"(b[0]), "r"(b[1]));
}

__device__ __forceinline__ void cp16(uint32_t saddr, const void* g) {
    asm volatile("cp.async.cg.shared.global [%0], [%1], 16;" :: "r"(saddr), "l"(g));
}
__device__ __forceinline__ void cp_commit() { asm volatile("cp.async.commit_group;"); }
__device__ __forceinline__ void cp_wait0()  { asm volatile("cp.async.wait_group 0;"); }

// ---------------------------------------------------------------------------
// Pre-round: out[i] = tf32_rna(in[i]) (vectorized)
// ---------------------------------------------------------------------------
__global__ void round_k(const float* __restrict__ in, float* __restrict__ out, int n4) {
    int i = blockIdx.x * blockDim.x + threadIdx.x;
    if (i < n4) {
        float4 v = ((const float4*)in)[i];
        v.x = roundtf(v.x); v.y = roundtf(v.y);
        v.z = roundtf(v.z); v.w = roundtf(v.w);
        ((float4*)out)[i] = v;
    }
}

// ---------------------------------------------------------------------------
// TF32 GEMM, inputs pre-rounded, cp.async double-buffered.
// C[M,N] = A[M,K]@B[K,N] (+bias); 128x128x32 tile, 256 thr, warp 32x64.
// Dynamic smem: As[2][128][36] + Bs[2][32][136] floats = 71680 B.
// ---------------------------------------------------------------------------
__global__ __launch_bounds__(256) void gemm_tf32_db(
    const float* __restrict__ A, const float* __restrict__ B,
    const float* __restrict__ bias, float* __restrict__ C,
    int M, int N, int K, int round_out)
{
    extern __shared__ float sg[];
    float* As = sg;                    // [2][128][36]
    float* Bs = sg + 2 * 128 * 36;     // [2][32][136]

    const int tid  = threadIdx.x;
    const int lane = tid & 31;
    const int wid  = tid >> 5;
    const int wm   = (wid & 3) * 32;
    const int wn   = (wid >> 2) * 64;
    const int g    = lane >> 2;
    const int q    = lane & 3;
    const int m0   = blockIdx.y * 128;
    const int n0   = blockIdx.x * 128;

    const uint32_t sA0 = (uint32_t)__cvta_generic_to_shared(As);
    const uint32_t sB0 = (uint32_t)__cvta_generic_to_shared(Bs);

    float acc[2][8][4];
#pragma unroll
    for (int mt = 0; mt < 2; mt++)
#pragma unroll
        for (int nt = 0; nt < 8; nt++)
#pragma unroll
            for (int i = 0; i < 4; i++) acc[mt][nt][i] = 0.f;

    // per-thread load coords
    const int ar = tid >> 3, ac = (tid & 7) * 4;     // A: 4 frags r+=32? no: f=tid+i*256
    const int br = tid >> 5, bc = (tid & 31) * 4;

    auto prefetch = [&](int kt, int buf) {
        const int k0 = kt * 32;
#pragma unroll
        for (int i = 0; i < 4; i++) {
            int r = ar + i * 32;                     // (tid + i*256)>>3
            cp16(sA0 + (uint32_t)((buf * 128 + r) * 36 + ac) * 4,
                 A + (size_t)(m0 + r) * K + k0 + ac);
        }
#pragma unroll
        for (int i = 0; i < 4; i++) {
            int r = br + i * 8;                      // (tid + i*256)>>5
            cp16(sB0 + (uint32_t)((buf * 32 + r) * 136 + bc) * 4,
                 B + (size_t)(k0 + r) * N + n0 + bc);
        }
    };

    prefetch(0, 0);
    cp_commit();

    const int KT = K / 32;
    for (int kt = 0; kt < KT; kt++) {
        cp_wait0();
        __syncthreads();
        if (kt + 1 < KT) { prefetch(kt + 1, (kt + 1) & 1); cp_commit(); }

        const float* Ab = As + (kt & 1) * 128 * 36;
        const float* Bb = Bs + (kt & 1) * 32 * 136;
#pragma unroll
        for (int kk = 0; kk < 4; kk++) {
            uint32_t a[2][4], b[8][2];
#pragma unroll
            for (int mt = 0; mt < 2; mt++) {
                int r = wm + mt * 16 + g;
                a[mt][0] = __float_as_uint(Ab[r * 36 + kk * 8 + q]);
                a[mt][1] = __float_as_uint(Ab[(r + 8) * 36 + kk * 8 + q]);
                a[mt][2] = __float_as_uint(Ab[r * 36 + kk * 8 + q + 4]);
                a[mt][3] = __float_as_uint(Ab[(r + 8) * 36 + kk * 8 + q + 4]);
            }
#pragma unroll
            for (int nt = 0; nt < 8; nt++) {
                int c = wn + nt * 8 + g;
                b[nt][0] = __float_as_uint(Bb[(kk * 8 + q) * 136 + c]);
                b[nt][1] = __float_as_uint(Bb[(kk * 8 + q + 4) * 136 + c]);
            }
#pragma unroll
            for (int mt = 0; mt < 2; mt++)
#pragma unroll
                for (int nt = 0; nt < 8; nt++)
                    mma8(acc[mt][nt], a[mt], b[nt]);
        }
        __syncthreads();
    }

#pragma unroll
    for (int mt = 0; mt < 2; mt++) {
#pragma unroll
        for (int nt = 0; nt < 8; nt++) {
            int row = m0 + wm + mt * 16 + g;
            int col = n0 + wn + nt * 8 + 2 * q;
            float b0 = bias ? bias[col] : 0.f;
            float b1 = bias ? bias[col + 1] : 0.f;
            float v00 = acc[mt][nt][0] + b0, v01 = acc[mt][nt][1] + b1;
            float v10 = acc[mt][nt][2] + b0, v11 = acc[mt][nt][3] + b1;
            if (round_out) {
                v00 = roundtf(v00); v01 = roundtf(v01);
                v10 = roundtf(v10); v11 = roundtf(v11);
            }
            *(float2*)(C + (size_t)row * N + col)       = make_float2(v00, v01);
            *(float2*)(C + (size_t)(row + 8) * N + col) = make_float2(v10, v11);
        }
    }
}

// ---------------------------------------------------------------------------
// Flash attention, tf32 mma, cp.async double-buffered K/V, pre-rounded qkv.
// Grid (S/64, B*H), 128 thr = 4 warps, warp owns 16 query rows.
// Scale 1/8 folded into softmax exponent (exact).
// Dyn smem floats: Qs[64][68] + Ks[2][64][68] + Vs[2][64][72] + Ps[64][68]
//   = 26624 floats = 106496 B.
// ---------------------------------------------------------------------------
#define AQS 0
#define AKS (64 * 68)
#define AVS (AKS + 2 * 64 * 68)
#define APS (AVS + 2 * 64 * 72)
#define ASM_FLOATS (APS + 64 * 68)

__global__ __launch_bounds__(128) void attn_tf32_db(
    const float* __restrict__ qkv, float* __restrict__ out)
{
    extern __shared__ float sf[];
    float* Qs = sf + AQS;
    float* Ks = sf + AKS;   // [2][64][68]
    float* Vs = sf + AVS;   // [2][64][72]
    float* Ps = sf + APS;

    const int tid  = threadIdx.x;
    const int lane = tid & 31;
    const int wid  = tid >> 5;
    const int g    = lane >> 2;
    const int q    = lane & 3;
    const int wr   = wid * 16;
    const int bh   = blockIdx.y;
    const int b    = bh >> 4;
    const int h    = bh & 15;
    const int q0   = blockIdx.x * 64;

    const float* Qg = qkv + (size_t)b * S_LEN * QKV_N + h * DK;
    const float* Kg = Qg + DMODEL;
    const float* Vg = Qg + 2 * DMODEL;

    const uint32_t sQ = (uint32_t)__cvta_generic_to_shared(Qs);
    const uint32_t sK = (uint32_t)__cvta_generic_to_shared(Ks);
    const uint32_t sV = (uint32_t)__cvta_generic_to_shared(Vs);

    const int lr = tid >> 4, lc = (tid & 15) * 4;   // 8 rows per pass

    // prologue: Q tile + KV tile 0
#pragma unroll
    for (int i = 0; i < 8; i++) {
        int r = lr + i * 8;
        cp16(sQ + (uint32_t)(r * 68 + lc) * 4, Qg + (size_t)(q0 + r) * QKV_N + lc);
    }
#pragma unroll
    for (int i = 0; i < 8; i++) {
        int r = lr + i * 8;
        cp16(sK + (uint32_t)(r * 68 + lc) * 4, Kg + (size_t)r * QKV_N + lc);
        cp16(sV + (uint32_t)(r * 72 + lc) * 4, Vg + (size_t)r * QKV_N + lc);
    }
    cp_commit();

    float m_i[2] = {-1e30f, -1e30f};
    float l_i[2] = {0.f, 0.f};
    float o[8][4];
#pragma unroll
    for (int nt = 0; nt < 8; nt++)
#pragma unroll
        for (int i = 0; i < 4; i++) o[nt][i] = 0.f;

    const int NT = S_LEN / 64;
    for (int kt = 0; kt < NT; kt++) {
        cp_wait0();
        __syncthreads();
        if (kt + 1 < NT) {
            int buf = (kt + 1) & 1;
            const float* Kn = Kg + (size_t)(kt + 1) * 64 * QKV_N;
            const float* Vn = Vg + (size_t)(kt + 1) * 64 * QKV_N;
#pragma unroll
            for (int i = 0; i < 8; i++) {
                int r = lr + i * 8;
                cp16(sK + (uint32_t)((buf * 64 + r) * 68 + lc) * 4, Kn + (size_t)r * QKV_N + lc);
                cp16(sV + (uint32_t)((buf * 64 + r) * 72 + lc) * 4, Vn + (size_t)r * QKV_N + lc);
            }
            cp_commit();
        }
        const float* Kb = Ks + (kt & 1) * 64 * 68;
        const float* Vb = Vs + (kt & 1) * 64 * 72;

        // ---- S = Q K^T (raw scale) ----
        float sacc[8][4];
#pragma unroll
        for (int nt = 0; nt < 8; nt++)
#pragma unroll
            for (int i = 0; i < 4; i++) sacc[nt][i] = 0.f;

#pragma unroll
        for (int kk = 0; kk < 8; kk++) {
            uint32_t a[4], bf[2];
            int r = wr + g;
            a[0] = __float_as_uint(Qs[r * 68 + kk * 8 + q]);
            a[1] = __float_as_uint(Qs[(r + 8) * 68 + kk * 8 + q]);
            a[2] = __float_as_uint(Qs[r * 68 + kk * 8 + q + 4]);
            a[3] = __float_as_uint(Qs[(r + 8) * 68 + kk * 8 + q + 4]);
#pragma unroll
            for (int nt = 0; nt < 8; nt++) {
                bf[0] = __float_as_uint(Kb[(nt * 8 + g) * 68 + kk * 8 + q]);
                bf[1] = __float_as_uint(Kb[(nt * 8 + g) * 68 + kk * 8 + q + 4]);
                mma8(sacc[nt], a, bf);
            }
        }

        // ---- online softmax; true score = raw * 0.125 ----
#pragma unroll
        for (int rh = 0; rh < 2; rh++) {
            int row = wr + g + 8 * rh;
            float rm = -1e30f;
#pragma unroll
            for (int nt = 0; nt < 8; nt++)
                rm = fmaxf(rm, fmaxf(sacc[nt][2 * rh], sacc[nt][2 * rh + 1]));
            rm = fmaxf(rm, __shfl_xor_sync(0xffffffffu, rm, 1));
            rm = fmaxf(rm, __shfl_xor_sync(0xffffffffu, rm, 2));

            float mnew = fmaxf(m_i[rh], rm);
            float corr = __expf((m_i[rh] - mnew) * 0.125f);
            m_i[rh] = mnew;

            float rs = 0.f;
#pragma unroll
            for (int nt = 0; nt < 8; nt++) {
                float p0 = __expf((sacc[nt][2 * rh] - mnew) * 0.125f);
                float p1 = __expf((sacc[nt][2 * rh + 1] - mnew) * 0.125f);
                Ps[row * 68 + nt * 8 + 2 * q]     = roundtf(p0);
                Ps[row * 68 + nt * 8 + 2 * q + 1] = roundtf(p1);
                rs += p0 + p1;
            }
            rs += __shfl_xor_sync(0xffffffffu, rs, 1);
            rs += __shfl_xor_sync(0xffffffffu, rs, 2);
            l_i[rh] = l_i[rh] * corr + rs;
#pragma unroll
            for (int nt = 0; nt < 8; nt++) {
                o[nt][2 * rh]     *= corr;
                o[nt][2 * rh + 1] *= corr;
            }
        }
        __syncwarp();   // Ps rows are warp-private

        // ---- O += P V ----
#pragma unroll
        for (int kk = 0; kk < 8; kk++) {
            uint32_t a[4], bf[2];
            int r = wr + g;
            a[0] = __float_as_uint(Ps[r * 68 + kk * 8 + q]);
            a[1] = __float_as_uint(Ps[(r + 8) * 68 + kk * 8 + q]);
            a[2] = __float_as_uint(Ps[r * 68 + kk * 8 + q + 4]);
            a[3] = __float_as_uint(Ps[(r + 8) * 68 + kk * 8 + q + 4]);
#pragma unroll
            for (int nt = 0; nt < 8; nt++) {
                bf[0] = __float_as_uint(Vb[(kk * 8 + q) * 72 + nt * 8 + g]);
                bf[1] = __float_as_uint(Vb[(kk * 8 + q + 4) * 72 + nt * 8 + g]);
                mma8(o[nt], a, bf);
            }
        }
    }

    // ---- normalize + write (tf32-rounded for GEMM2) ----
#pragma unroll
    for (int rh = 0; rh < 2; rh++) {
        float inv = 1.f / l_i[rh];
        int token = b * S_LEN + q0 + wr + g + 8 * rh;
        float* op = out + (size_t)token * DMODEL + h * DK;
#pragma unroll
        for (int nt = 0; nt < 8; nt++) {
            float2 v = make_float2(roundtf(o[nt][2 * rh] * inv),
                                   roundtf(o[nt][2 * rh + 1] * inv));
            *(float2*)(op + nt * 8 + 2 * q) = v;
        }
    }
}

// ---------------------------------------------------------------------------
extern "C" void kernel_launch(void* const* d_in, const int* in_sizes, int n_in,
                              void* d_out, int out_size)
{
    const float* input = (const float*)d_in[0];
    const float* W_qkv = (const float*)d_in[1];
    const float* b_qkv = (const float*)d_in[2];
    const float* W_out = (const float*)d_in[3];
    float* out = (float*)d_out;

    float *qkv_buf, *att_buf, *in_r, *wqkv_r, *wout_r;
    cudaGetSymbolAddress((void**)&qkv_buf, g_qkv);
    cudaGetSymbolAddress((void**)&att_buf, g_att);
    cudaGetSymbolAddress((void**)&in_r,   g_in_r);
    cudaGetSymbolAddress((void**)&wqkv_r, g_wqkv_r);
    cudaGetSymbolAddress((void**)&wout_r, g_wout_r);

    // 0) pre-round inputs/weights to tf32 grid
    {
        int n1 = NTOK * DMODEL / 4, n2 = DMODEL * QKV_N / 4, n3 = DMODEL * DMODEL / 4;
        round_k<<<(n1 + 255) / 256, 256>>>(input, in_r, n1);
        round_k<<<(n2 + 255) / 256, 256>>>(W_qkv, wqkv_r, n2);
        round_k<<<(n3 + 255) / 256, 256>>>(W_out, wout_r, n3);
    }

    const int gsmem = 2 * (128 * 36 + 32 * 136) * (int)sizeof(float);   // 71680
    cudaFuncSetAttribute(gemm_tf32_db,
                         cudaFuncAttributeMaxDynamicSharedMemorySize, gsmem);

    // 1) QKV projection + bias (output tf32-rounded)
    gemm_tf32_db<<<dim3(QKV_N / 128, NTOK / 128), 256, gsmem>>>(
        in_r, wqkv_r, b_qkv, qkv_buf, NTOK, QKV_N, DMODEL, 1);

    // 2) Flash attention
    const int asmem = ASM_FLOATS * (int)sizeof(float);   // 106496
    cudaFuncSetAttribute(attn_tf32_db,
                         cudaFuncAttributeMaxDynamicSharedMemorySize, asmem);
    attn_tf32_db<<<dim3(S_LEN / 64, BATCH * NHEADS), 128, asmem>>>(qkv_buf, att_buf);

    // 3) Output projection
    gemm_tf32_db<<<dim3(DMODEL / 128, NTOK / 128), 256, gsmem>>>(
        att_buf, wout_r, nullptr, out, NTOK, DMODEL, DMODEL, 0);
}